// round 13
// baseline (speedup 1.0000x reference)
#include <cuda_runtime.h>
#include <cstdint>

// SpectralNetLoss: W [8192,8192] f32, Y [8192,32] f32 -> scalar f32.
// WY = W @ Y and d = W @ 1 in ONE tf32 GEMM (mma.sync m16n8k8, sm_80 baseline
// ISA — harness targets sm_103 without 'a'; no tcgen05/TMA).
// B' = [Y^T ; ones] (40 x 8192) pre-fragmented per 64-k tile (LDS.128 reads).
// Grid (64 rb x 4 ksplit). KT=64 -> 256B contiguous per W row per visit.
// Loss fused into the GEMM: last CTA per row-block computes its contribution.

#define MDIM    8192
#define KDIM    32
#define NB      40                  // 32 Y cols + 8 ones cols (row sums d)
#define MT      128                 // rows per row-block
#define KT      64                  // K per tile
#define NRB     (MDIM / MT)         // 64 row-blocks
#define NKT     (MDIM / KT)         // 128 k-tiles total
#define KSPLIT  4
#define KRANGE  (MDIM / KSPLIT)     // 2048
#define TILES   (KRANGE / KT)       // 32 per CTA
#define STAGES  2
#define THREADS 128

#define PITCH     68                         // W smem row pitch (64 + 4 pad)
#define A_TILE_F  (MT * PITCH)               // 8704 floats
#define BFRAG_F   (NB * KT)                  // 2560 floats per k-tile
#define STAGE_F   (A_TILE_F + BFRAG_F)       // 11264 floats
#define STAGE_B   (STAGE_F * 4)              // 45056 B
#define DYN_SMEM  (STAGES * STAGE_B)         // 90112 B (2 CTAs/SM fits)

// Scratch (no device allocs allowed).
__device__ float g_B[NKT * BFRAG_F];          // fragmented B', 1.25 MB
__device__ float g_wy[MDIM * KDIM];           // final WY accumulator, 1 MB
__device__ float g_d[MDIM];                   // final row sums, 32 KB
__device__ int   g_cnt[NRB];                  // per-row-block completion count

__device__ __forceinline__ uint32_t smem_u32(const void* p) {
    return (uint32_t)__cvta_generic_to_shared(p);
}
__device__ __forceinline__ void cp_async16(uint32_t dst, const void* src) {
    asm volatile("cp.async.cg.shared.global [%0], [%1], 16;\n" :: "r"(dst), "l"(src));
}
#define CP_COMMIT() asm volatile("cp.async.commit_group;\n" ::: "memory")
#define CP_WAIT(n)  asm volatile("cp.async.wait_group %0;\n" :: "n"(n) : "memory")

__device__ __forceinline__ void mma_tf32(float* c, const uint32_t* a, uint32_t b0,
                                         uint32_t b1) {
    asm volatile(
        "mma.sync.aligned.m16n8k8.row.col.f32.tf32.tf32.f32 "
        "{%0,%1,%2,%3}, {%4,%5,%6,%7}, {%8,%9}, {%0,%1,%2,%3};"
        : "+f"(c[0]), "+f"(c[1]), "+f"(c[2]), "+f"(c[3])
        : "r"(a[0]), "r"(a[1]), "r"(a[2]), "r"(a[3]), "r"(b0), "r"(b1));
}

// ---------------------------------------------------------------------------
// Prep: build fragmented B' (coalesced), zero g_wy / g_d / g_cnt / out.
// Fragment flat index f (0..2559) -> (nt,ks2,g,tig,e):
//   f = (((nt*4+ks2)*8+g)*4+tig)*4+e,  n = nt*8+g,
//   k_local = (2*ks2+(e>>1))*8 + tig + (e&1)*4,  value = (n<32)?Y[k][n]:1.
// Compute contract per (nt,ks2): thread lid LDS.128 at ((nt*4+ks2)*32+lid)*4
// yields {B[n][2*ks2*8+tig], +4, B[n][(2*ks2+1)*8+tig], +4}.
// ---------------------------------------------------------------------------
__global__ void __launch_bounds__(256)
prep_kernel(const float* __restrict__ Y, float* __restrict__ out) {
    __shared__ float Ys[KT][KDIM + 1];
    const int t   = blockIdx.x;          // k-tile 0..127
    const int tid = threadIdx.x;

    {   // coalesced 64x32 Y tile load (512 float4)
        const float4* src = (const float4*)(Y + (size_t)t * KT * KDIM);
        #pragma unroll
        for (int q = 0; q < 2; ++q) {
            int idx = tid + q * 256;
            float4 v = src[idx];
            int j = idx >> 3, c = (idx & 7) * 4;
            Ys[j][c] = v.x; Ys[j][c+1] = v.y; Ys[j][c+2] = v.z; Ys[j][c+3] = v.w;
        }
    }
    __syncthreads();

    float* dst = g_B + (size_t)t * BFRAG_F;
    #pragma unroll
    for (int p = 0; p < BFRAG_F / 256; ++p) {        // 10 coalesced bursts
        int f   = tid + p * 256;
        int e   = f & 3;
        int tig = (f >> 2) & 3;
        int g   = (f >> 4) & 7;
        int ks2 = (f >> 7) & 3;
        int nt  = f >> 9;
        int n   = nt * 8 + g;
        int kl  = (2 * ks2 + (e >> 1)) * 8 + tig + (e & 1) * 4;
        dst[f] = (n < KDIM) ? Ys[kl][n] : 1.0f;
    }

    // zero accumulators: 128 blocks x 256 thr x 2 float4 == 262144 floats
    #pragma unroll
    for (int q = 0; q < 2; ++q)
        ((float4*)g_wy)[(t * 256 + tid) * 2 + q] = make_float4(0.f, 0.f, 0.f, 0.f);
    if (t < 32) g_d[t * 256 + tid] = 0.0f;
    if (t == 0 && tid < NRB) g_cnt[tid] = 0;
    if (t == 0 && tid == 0) out[0] = 0.0f;
}

// ---------------------------------------------------------------------------
// Main GEMM + fused loss. CTA (rb, ks): D[128 x 40] over K range, atomic
// accumulate; last CTA of each row-block computes the loss contribution.
// ---------------------------------------------------------------------------
__global__ void __launch_bounds__(THREADS)
mma_main(const float* __restrict__ W, const float* __restrict__ Y,
         float* __restrict__ out) {
    extern __shared__ float sm[];
    __shared__ int s_last;
    __shared__ float s_red[4];

    const int tid  = threadIdx.x;
    const int wid  = tid >> 5;
    const int lid  = tid & 31;
    const int g    = lid >> 2;
    const int tig  = lid & 3;
    const int rb   = blockIdx.x;
    const int row0 = rb * MT;
    const int kb0  = blockIdx.y * KRANGE;
    const int tg0  = kb0 / KT;           // first global k-tile index

    const uint32_t sbase = smem_u32(sm);

    float acc[2][5][4];
    #pragma unroll
    for (int mh = 0; mh < 2; ++mh)
        #pragma unroll
        for (int nt = 0; nt < 5; ++nt)
            #pragma unroll
            for (int q = 0; q < 4; ++q) acc[mh][nt][q] = 0.0f;

    // ---- stage loader: W 128x64 (pitch 68) + fragmented B (linear 10KB) ----
    auto load_tile = [&](int t) {
        const uint32_t sb   = sbase + (t & 1) * STAGE_B;
        const float*   wsrc = W + (size_t)row0 * MDIM + kb0 + t * KT;
        #pragma unroll
        for (int p = 0; p < 16; ++p) {                   // W: 2048 x 16B chunks
            int c = tid + p * 128;
            int r = c >> 4, ci = c & 15;
            cp_async16(sb + (r * PITCH + ci * 4) * 4,
                       wsrc + (size_t)r * MDIM + ci * 4);
        }
        const float* bsrc = g_B + (size_t)(tg0 + t) * BFRAG_F;
        #pragma unroll
        for (int p = 0; p < 5; ++p) {                    // B: 640 x 16B chunks
            int c = tid + p * 128;
            cp_async16(sb + A_TILE_F * 4 + c * 16, bsrc + c * 4);
        }
    };

    load_tile(0);
    CP_COMMIT();

    for (int t = 0; t < TILES; ++t) {
        if (t + 1 < TILES) load_tile(t + 1);
        CP_COMMIT();
        CP_WAIT(1);                          // tile t resident
        __syncthreads();

        const float* As = sm + (t & 1) * STAGE_F + (wid * 32 + g) * PITCH;
        const float* Bs = sm + (t & 1) * STAGE_F + A_TILE_F;

        #pragma unroll
        for (int ks2 = 0; ks2 < 4; ++ks2) {
            float4 b4[5];
            #pragma unroll
            for (int nt = 0; nt < 5; ++nt)
                b4[nt] = *(const float4*)&Bs[((nt * 4 + ks2) * 32 + lid) * 4];

            #pragma unroll
            for (int sub = 0; sub < 2; ++sub) {
                const int k0 = (ks2 * 2 + sub) * 8;
                uint32_t a0[4], a1[4];
                a0[0] = __float_as_uint(As[k0 + tig]);
                a0[1] = __float_as_uint(As[8 * PITCH + k0 + tig]);
                a0[2] = __float_as_uint(As[k0 + tig + 4]);
                a0[3] = __float_as_uint(As[8 * PITCH + k0 + tig + 4]);
                a1[0] = __float_as_uint(As[16 * PITCH + k0 + tig]);
                a1[1] = __float_as_uint(As[24 * PITCH + k0 + tig]);
                a1[2] = __float_as_uint(As[16 * PITCH + k0 + tig + 4]);
                a1[3] = __float_as_uint(As[24 * PITCH + k0 + tig + 4]);
                #pragma unroll
                for (int nt = 0; nt < 5; ++nt) {
                    uint32_t b0 = __float_as_uint(sub ? b4[nt].z : b4[nt].x);
                    uint32_t b1 = __float_as_uint(sub ? b4[nt].w : b4[nt].y);
                    mma_tf32(acc[0][nt], a0, b0, b1);
                    mma_tf32(acc[1][nt], a1, b0, b1);
                }
            }
        }
        __syncthreads();
    }

    // ---- flush: atomic accumulate into final g_wy / g_d ----
    #pragma unroll
    for (int mh = 0; mh < 2; ++mh) {
        const int rA = row0 + wid * 32 + mh * 16 + g;
        const int rB = rA + 8;
        #pragma unroll
        for (int nt = 0; nt < 4; ++nt) {
            int col = nt * 8 + 2 * tig;
            atomicAdd(&g_wy[(size_t)rA * KDIM + col],     acc[mh][nt][0]);
            atomicAdd(&g_wy[(size_t)rA * KDIM + col + 1], acc[mh][nt][1]);
            atomicAdd(&g_wy[(size_t)rB * KDIM + col],     acc[mh][nt][2]);
            atomicAdd(&g_wy[(size_t)rB * KDIM + col + 1], acc[mh][nt][3]);
        }
        if (tig == 0) {
            atomicAdd(&g_d[rA], acc[mh][4][0]);
            atomicAdd(&g_d[rB], acc[mh][4][2]);
        }
    }

    // ---- fused loss: last CTA of this row-block computes its contribution ----
    __threadfence();
    __syncthreads();
    if (tid == 0) s_last = (atomicAdd(&g_cnt[rb], 1) == KSPLIT - 1);
    __syncthreads();
    if (s_last) {
        __threadfence();                     // acquire side
        const int row = row0 + tid;          // 128 threads, one row each
        float dinv = 1.0f / __ldcg(&g_d[row]);
        float s = 0.0f;
        #pragma unroll
        for (int k = 0; k < KDIM; ++k) {
            float y = Y[(size_t)row * KDIM + k];
            s += y * (y - __ldcg(&g_wy[(size_t)row * KDIM + k]) * dinv);
        }
        #pragma unroll
        for (int o = 16; o; o >>= 1) s += __shfl_xor_sync(0xffffffffu, s, o);
        if (lid == 0) s_red[wid] = s;
        __syncthreads();
        if (tid == 0) {
            float tot = s_red[0] + s_red[1] + s_red[2] + s_red[3];
            atomicAdd(out, tot * (1.0f / (float)MDIM));
        }
    }
}

// ---------------------------------------------------------------------------
extern "C" void kernel_launch(void* const* d_in, const int* in_sizes, int n_in,
                              void* d_out, int out_size) {
    const float* W = (const float*)d_in[0];
    const float* Y = (const float*)d_in[1];
    float* out = (float*)d_out;

    cudaFuncSetAttribute(mma_main, cudaFuncAttributeMaxDynamicSharedMemorySize,
                         DYN_SMEM);

    prep_kernel<<<NKT, 256>>>(Y, out);               // 128 blocks

    dim3 grid(NRB, KSPLIT);                          // (64, 4) = 256 CTAs
    mma_main<<<grid, THREADS, DYN_SMEM>>>(W, Y, out);
}